// round 1
// baseline (speedup 1.0000x reference)
#include <cuda_runtime.h>
#include <math.h>

// ---------------------------------------------------------------------------
// PhysicsEmbedding: algebraic collapse of the whole pipeline.
//   B=32, S=4096, D=1024, H=256
// out[b,s,:] = A1·p[b,s] + A2·vel[b,s] + A3·acc[b,s] + g[b,:]
// where A1=Wo[:,0:256]@Wp (1024x2), A2=Wo[:,256:512]@Wv, A3=Wo[:,512:768]@Wa,
//       A4=Wo[:,768:1024]@Wf (1024x32),
//       c = bo + Wo1@bp + Wo2@bv + Wo3@ba + Wo4@bf,
//       g[b,:] = A4 @ freq[b] + c  (freq = |16-bin DFT| per channel, [32])
// ---------------------------------------------------------------------------

#define B_ 32
#define S_ 4096
#define D_ 1024
#define H_ 256
#define SCHUNK 16

// Scratch (device globals; no allocation allowed)
__device__ float g_freq[B_ * 32];        // |DFT bins|, [b][j], j = c*16+k
__device__ float g_a1x[D_], g_a1y[D_];
__device__ float g_a2x[D_], g_a2y[D_];
__device__ float g_a3x[D_], g_a3y[D_];
__device__ float g_A4[D_ * 32];
__device__ float g_cbias[D_];
__device__ float g_g[B_ * D_];           // per-batch constant vector

// ---------------------------------------------------------------------------
// 1) Direct 16-bin DFT magnitude per (batch, channel).
//    grid (32 j, 32 b), 256 threads reduce over t=0..4095.
// ---------------------------------------------------------------------------
__global__ void dft_kernel(const float* __restrict__ pattern) {
    int j = blockIdx.x;          // 0..31 : j = c*16 + k
    int b = blockIdx.y;
    int c = j >> 4;
    int k = j & 15;
    int tid = threadIdx.x;

    float re = 0.f, im = 0.f;
    for (int t = tid; t < S_; t += 256) {
        float x = pattern[((size_t)b * S_ + t) * 2 + c];
        // angle in units of pi: -2*k*t/4096 = -(k*t)/2048  (exact in fp32)
        float a = (float)(k * t) * (-1.0f / 2048.0f);
        float sn, cs;
        sincospif(a, &sn, &cs);
        re += x * cs;
        im += x * sn;
    }
    __shared__ float sre[256], sim[256];
    sre[tid] = re; sim[tid] = im;
    __syncthreads();
    for (int off = 128; off > 0; off >>= 1) {
        if (tid < off) { sre[tid] += sre[tid + off]; sim[tid] += sim[tid + off]; }
        __syncthreads();
    }
    if (tid == 0) {
        float rr = sre[0], ii = sim[0];
        g_freq[b * 32 + j] = sqrtf(rr * rr + ii * ii);
    }
}

// ---------------------------------------------------------------------------
// 2) Fold the small matrices through Wo. One warp per output row d.
// ---------------------------------------------------------------------------
__global__ void coeff_kernel(const float* __restrict__ Wp, const float* __restrict__ bp,
                             const float* __restrict__ Wv, const float* __restrict__ bv,
                             const float* __restrict__ Wa, const float* __restrict__ ba,
                             const float* __restrict__ Wf, const float* __restrict__ bfr,
                             const float* __restrict__ Wo, const float* __restrict__ bo) {
    int d = blockIdx.x;
    int lane = threadIdx.x;          // 32 threads
    const float* wo = Wo + (size_t)d * D_;

    float a1x = 0, a1y = 0, a2x = 0, a2y = 0, a3x = 0, a3y = 0, bias = 0;
    float a4[32];
#pragma unroll
    for (int j = 0; j < 32; j++) a4[j] = 0.f;

    for (int h = lane; h < H_; h += 32) {
        float w0 = wo[h];
        float w1 = wo[256 + h];
        float w2 = wo[512 + h];
        float w3 = wo[768 + h];
        a1x += w0 * Wp[h * 2 + 0];  a1y += w0 * Wp[h * 2 + 1];
        a2x += w1 * Wv[h * 2 + 0];  a2y += w1 * Wv[h * 2 + 1];
        a3x += w2 * Wa[h * 2 + 0];  a3y += w2 * Wa[h * 2 + 1];
        bias += w0 * bp[h] + w1 * bv[h] + w2 * ba[h] + w3 * bfr[h];
#pragma unroll
        for (int j = 0; j < 32; j++) a4[j] += w3 * Wf[h * 32 + j];
    }

#pragma unroll
    for (int off = 16; off > 0; off >>= 1) {
        a1x += __shfl_down_sync(0xffffffffu, a1x, off);
        a1y += __shfl_down_sync(0xffffffffu, a1y, off);
        a2x += __shfl_down_sync(0xffffffffu, a2x, off);
        a2y += __shfl_down_sync(0xffffffffu, a2y, off);
        a3x += __shfl_down_sync(0xffffffffu, a3x, off);
        a3y += __shfl_down_sync(0xffffffffu, a3y, off);
        bias += __shfl_down_sync(0xffffffffu, bias, off);
    }
#pragma unroll
    for (int j = 0; j < 32; j++) {
        float v = a4[j];
#pragma unroll
        for (int off = 16; off > 0; off >>= 1)
            v += __shfl_down_sync(0xffffffffu, v, off);
        if (lane == 0) g_A4[d * 32 + j] = v;
    }
    if (lane == 0) {
        g_a1x[d] = a1x; g_a1y[d] = a1y;
        g_a2x[d] = a2x; g_a2y[d] = a2y;
        g_a3x[d] = a3x; g_a3y[d] = a3y;
        g_cbias[d] = bias + bo[d];
    }
}

// ---------------------------------------------------------------------------
// 3) Per-batch constant vector g[b,d] = c[d] + A4[d,:]·freq[b,:]
// ---------------------------------------------------------------------------
__global__ void gtab_kernel() {
    int b = blockIdx.x;
    int tid = threadIdx.x;           // 256 threads, 4 d's each
    __shared__ float fr[32];
    if (tid < 32) fr[tid] = g_freq[b * 32 + tid];
    __syncthreads();
#pragma unroll
    for (int i = 0; i < 4; i++) {
        int d = tid * 4 + i;
        float acc = g_cbias[d];
        const float* a4 = g_A4 + d * 32;
#pragma unroll
        for (int j = 0; j < 32; j++) acc += a4[j] * fr[j];
        g_g[b * D_ + d] = acc;
    }
}

// ---------------------------------------------------------------------------
// 4) Main write kernel. One block covers D=1024 (256 thr x float4) for a
//    chunk of SCHUNK timesteps. Coefficients live in registers; pattern
//    chunk staged in shared once per block. Purely HBM-write bound.
// ---------------------------------------------------------------------------
__global__ void __launch_bounds__(256) main_kernel(const float* __restrict__ pattern,
                                                   float* __restrict__ out) {
    int b = blockIdx.y;
    int s0 = blockIdx.x * SCHUNK;
    int tid = threadIdx.x;
    int d = tid * 4;

    __shared__ float sp[(SCHUNK + 2) * 2];   // pattern[b, s0-2 .. s0+SCHUNK-1]
    if (tid < (SCHUNK + 2) * 2) {
        int s = s0 - 2 + (tid >> 1);
        int c = tid & 1;
        sp[tid] = (s >= 0) ? pattern[((size_t)b * S_ + s) * 2 + c] : 0.0f;
    }

    float4 k1x = *(const float4*)(g_a1x + d);
    float4 k1y = *(const float4*)(g_a1y + d);
    float4 k2x = *(const float4*)(g_a2x + d);
    float4 k2y = *(const float4*)(g_a2y + d);
    float4 k3x = *(const float4*)(g_a3x + d);
    float4 k3y = *(const float4*)(g_a3y + d);
    float4 gg  = *(const float4*)(g_g + b * D_ + d);
    __syncthreads();

    float* op = out + ((size_t)b * S_ + s0) * D_ + d;

#pragma unroll
    for (int i = 0; i < SCHUNK; i++) {
        int s = s0 + i;
        float px = sp[(i + 2) * 2 + 0], py = sp[(i + 2) * 2 + 1];
        float mx = sp[(i + 1) * 2 + 0], my = sp[(i + 1) * 2 + 1];
        float nx = sp[(i + 0) * 2 + 0], ny = sp[(i + 0) * 2 + 1];

        float vx, vy, ax_, ay_;
        if (s == 0) {
            vx = 0.f; vy = 0.f; ax_ = 0.f; ay_ = 0.f;
        } else if (s == 1) {
            vx = px - mx; vy = py - my; ax_ = vx; ay_ = vy;
        } else {
            vx = px - mx; vy = py - my;
            ax_ = px - 2.f * mx + nx; ay_ = py - 2.f * my + ny;
        }

        float4 o;
        o.x = gg.x + k1x.x * px + k1y.x * py + k2x.x * vx + k2y.x * vy + k3x.x * ax_ + k3y.x * ay_;
        o.y = gg.y + k1x.y * px + k1y.y * py + k2x.y * vx + k2y.y * vy + k3x.y * ax_ + k3y.y * ay_;
        o.z = gg.z + k1x.z * px + k1y.z * py + k2x.z * vx + k2y.z * vy + k3x.z * ax_ + k3y.z * ay_;
        o.w = gg.w + k1x.w * px + k1y.w * py + k2x.w * vx + k2y.w * vy + k3x.w * ax_ + k3y.w * ay_;

        *(float4*)(op + (size_t)i * D_) = o;
    }
}

// ---------------------------------------------------------------------------
extern "C" void kernel_launch(void* const* d_in, const int* in_sizes, int n_in,
                              void* d_out, int out_size) {
    const float* pattern = (const float*)d_in[0];
    const float* Wp  = (const float*)d_in[1];
    const float* bp  = (const float*)d_in[2];
    const float* Wv  = (const float*)d_in[3];
    const float* bv  = (const float*)d_in[4];
    const float* Wa  = (const float*)d_in[5];
    const float* ba  = (const float*)d_in[6];
    const float* Wf  = (const float*)d_in[7];
    const float* bfr = (const float*)d_in[8];
    const float* Wo  = (const float*)d_in[9];
    const float* bo  = (const float*)d_in[10];
    float* out = (float*)d_out;

    dft_kernel<<<dim3(32, B_), 256>>>(pattern);
    coeff_kernel<<<D_, 32>>>(Wp, bp, Wv, bv, Wa, ba, Wf, bfr, Wo, bo);
    gtab_kernel<<<B_, 256>>>();
    main_kernel<<<dim3(S_ / SCHUNK, B_), 256>>>(pattern, out);
}